// round 1
// baseline (speedup 1.0000x reference)
#include <cuda_runtime.h>
#include <math_constants.h>

// Problem constants
#define BB    4
#define NN    1024      // src points per batch
#define MM    65536     // H*W target points per batch
#define CC    64        // desc channels
#define VCH   72        // padded V row stride (0..63 raw desc, 64..66 coords, 67 weight)
#define SCALE 1.5625f   // 1/(C*TEMP) = 1/(64*0.01)

#define TQ 64
#define TK 64
#define LDC 68          // padded smem row stride (floats), 272B = 16B aligned, conflict-free
#define KSPLIT 16
#define NBLK (BB*16*KSPLIT)   // 4 * (1024/64) * 16 = 1024 partial blocks

// Scratch (static __device__ arrays: allocation-free per harness rules)
__device__ float g_Q[BB*NN*CC];                       //  1 MB  [b][n][c]
__device__ float g_K[(size_t)BB*MM*CC];               // 64 MB  [b][m][c]
__device__ float g_V[(size_t)BB*MM*VCH];              // 75 MB  [b][m][cv]
__device__ float g_part[(size_t)NBLK*64*68];          // 18 MB  [blk][cv][q]
__device__ float g_pm[NBLK*64];
__device__ float g_pl[NBLK*64];

// ---------------------------------------------------------------------------
// Normalize src_desc -> Q  (zn over channel dim, ddof=1)
// ---------------------------------------------------------------------------
__global__ void norm_src_kernel(const float* __restrict__ src_desc) {
    int gid = blockIdx.x * blockDim.x + threadIdx.x;   // 4096 = B*N
    int b = gid >> 10, n = gid & 1023;
    const float* p = src_desc + (size_t)b * CC * NN + n;
    float xs[CC];
    float sum = 0.f;
#pragma unroll
    for (int c = 0; c < CC; c++) { xs[c] = p[c * NN]; sum += xs[c]; }
    float mean = sum * (1.f / 64.f);
    float var = 0.f;
#pragma unroll
    for (int c = 0; c < CC; c++) { float d = xs[c] - mean; var += d * d; }
    float inv = rsqrtf(var * (1.f / 63.f));
    float* q = g_Q + (size_t)gid * CC;
#pragma unroll
    for (int c = 0; c < CC; c++) q[c] = (xs[c] - mean) * inv;
}

// ---------------------------------------------------------------------------
// Normalize tgt_desc -> K ; pack V = [raw desc | coords | weight]
// ---------------------------------------------------------------------------
__global__ void norm_tgt_kernel(const float* __restrict__ tgt_desc,
                                const float* __restrict__ tgt_coords,
                                const float* __restrict__ tgt_w) {
    int gid = blockIdx.x * blockDim.x + threadIdx.x;   // 262144 = B*M
    int b = gid >> 16, m = gid & 65535;
    const float* p = tgt_desc + (size_t)b * CC * MM + m;
    float xs[CC];
    float sum = 0.f;
#pragma unroll
    for (int c = 0; c < CC; c++) { xs[c] = p[(size_t)c * MM]; sum += xs[c]; }
    float mean = sum * (1.f / 64.f);
    float var = 0.f;
#pragma unroll
    for (int c = 0; c < CC; c++) { float d = xs[c] - mean; var += d * d; }
    float inv = rsqrtf(var * (1.f / 63.f));
    float* kk = g_K + (size_t)gid * CC;
    float* vv = g_V + (size_t)gid * VCH;
#pragma unroll
    for (int c = 0; c < CC; c++) { kk[c] = (xs[c] - mean) * inv; vv[c] = xs[c]; }
    vv[64] = tgt_coords[(size_t)(b * 3 + 0) * MM + m];
    vv[65] = tgt_coords[(size_t)(b * 3 + 1) * MM + m];
    vv[66] = tgt_coords[(size_t)(b * 3 + 2) * MM + m];
    vv[67] = tgt_w[(size_t)b * MM + m];
}

// ---------------------------------------------------------------------------
// Fused flash attention, fp32, 4x4 register tiles, split-KV partials
// grid: (KSPLIT, N/TQ, B), block: 256
// ---------------------------------------------------------------------------
__global__ __launch_bounds__(256, 2) void attn_kernel() {
    extern __shared__ float sm[];
    float* Qs  = sm;                 // [64][LDC]  (q, c)
    float* Ks  = Qs  + TQ * LDC;     // [64][LDC]  (k, c)
    float* Ps  = Ks  + TK * LDC;     // [64][LDC]  (q, k)
    float* VsT = Ps  + TQ * LDC;     // [68][LDC]  (cv, k)
    float* mS  = VsT + 68 * LDC;     // [64]
    float* lS  = mS + 64;            // [64]
    float* cS  = lS + 64;            // [64]

    const int ks = blockIdx.x;       // key split 0..15
    const int qt = blockIdx.y;       // q tile 0..15
    const int b  = blockIdx.z;
    const int tid = threadIdx.x;
    const int ty = tid >> 4, tx = tid & 15;

    // Load Q tile (coalesced)
    const float* Qg = g_Q + ((size_t)b * NN + qt * TQ) * CC;
    for (int i = tid; i < TQ * CC; i += 256) {
        int q = i >> 6, c = i & 63;
        Qs[q * LDC + c] = Qg[q * CC + c];
    }
    if (tid < 64) { mS[tid] = -CUDART_INF_F; lS[tid] = 0.f; }

    float Oa[4][4];
#pragma unroll
    for (int i = 0; i < 4; i++)
#pragma unroll
        for (int j = 0; j < 4; j++) Oa[i][j] = 0.f;
    float Ob = 0.f;
    const int obq = tid >> 2;            // phase-2b query
    const int obc = 64 + (tid & 3);      // phase-2b channel (coords/weight)

    const int kbase = ks * (MM / KSPLIT);
    const float* Kg = g_K + ((size_t)b * MM + kbase) * CC;
    const float* Vg = g_V + ((size_t)b * MM + kbase) * VCH;

    __syncthreads();

    for (int kt = 0; kt < (MM / KSPLIT) / TK; kt++) {
        // ---- load K tile and V tile (V transposed to [cv][k]) ----
        const float* Kt = Kg + (size_t)(kt * TK) * CC;
        for (int i = tid; i < TK * CC; i += 256) {
            int k = i >> 6, c = i & 63;
            Ks[k * LDC + c] = Kt[k * CC + c];
        }
        const float* Vt = Vg + (size_t)(kt * TK) * VCH;
        for (int i = tid; i < TK * 68; i += 256) {
            int k = i / 68, cv = i - k * 68;
            VsT[cv * LDC + k] = Vt[k * VCH + cv];
        }
        __syncthreads();

        // ---- phase 1: S = Q K^T (4x4 per thread) ----
        float acc[4][4];
#pragma unroll
        for (int i = 0; i < 4; i++)
#pragma unroll
            for (int j = 0; j < 4; j++) acc[i][j] = 0.f;

        const float* qrow = Qs + (ty * 4) * LDC;
        const float* krow = Ks + (tx * 4) * LDC;
#pragma unroll
        for (int c4 = 0; c4 < CC; c4 += 4) {
            float4 av[4], bv[4];
#pragma unroll
            for (int i = 0; i < 4; i++) av[i] = *(const float4*)(qrow + i * LDC + c4);
#pragma unroll
            for (int j = 0; j < 4; j++) bv[j] = *(const float4*)(krow + j * LDC + c4);
#pragma unroll
            for (int i = 0; i < 4; i++)
#pragma unroll
                for (int j = 0; j < 4; j++)
                    acc[i][j] += av[i].x * bv[j].x + av[i].y * bv[j].y
                               + av[i].z * bv[j].z + av[i].w * bv[j].w;
        }

        // ---- online softmax bookkeeping (row groups owned by half-warps) ----
#pragma unroll
        for (int i = 0; i < 4; i++) {
            float rm = fmaxf(fmaxf(acc[i][0], acc[i][1]), fmaxf(acc[i][2], acc[i][3]));
#pragma unroll
            for (int off = 8; off > 0; off >>= 1)
                rm = fmaxf(rm, __shfl_xor_sync(0xffffffffu, rm, off));
            int q = ty * 4 + i;
            float mo = mS[q];
            float mn = fmaxf(mo, rm);
            float corr = __expf(SCALE * (mo - mn));   // -inf -> 0 on first tile
            float rs = 0.f;
#pragma unroll
            for (int j = 0; j < 4; j++) {
                float p = __expf(SCALE * (acc[i][j] - mn));
                Ps[q * LDC + tx * 4 + j] = p;
                rs += p;
            }
#pragma unroll
            for (int off = 8; off > 0; off >>= 1)
                rs += __shfl_xor_sync(0xffffffffu, rs, off);
            if (tx == 0) { mS[q] = mn; lS[q] = lS[q] * corr + rs; cS[q] = corr; }
        }
        __syncthreads();

        // ---- rescale accumulators ----
#pragma unroll
        for (int i = 0; i < 4; i++) {
            float cr = cS[ty * 4 + i];
#pragma unroll
            for (int j = 0; j < 4; j++) Oa[i][j] *= cr;
        }
        Ob *= cS[obq];

        // ---- phase 2a: O[q][0..63] += P V  (4x4 per thread) ----
        const float* prow = Ps + (ty * 4) * LDC;
        const float* vrow = VsT + (tx * 4) * LDC;
#pragma unroll
        for (int k4 = 0; k4 < TK; k4 += 4) {
            float4 pv[4], vv[4];
#pragma unroll
            for (int i = 0; i < 4; i++) pv[i] = *(const float4*)(prow + i * LDC + k4);
#pragma unroll
            for (int j = 0; j < 4; j++) vv[j] = *(const float4*)(vrow + j * LDC + k4);
#pragma unroll
            for (int i = 0; i < 4; i++)
#pragma unroll
                for (int j = 0; j < 4; j++)
                    Oa[i][j] += pv[i].x * vv[j].x + pv[i].y * vv[j].y
                              + pv[i].z * vv[j].z + pv[i].w * vv[j].w;
        }

        // ---- phase 2b: coords + weight channels (64..67) ----
        {
            const float* pb = Ps + obq * LDC;
            const float* vb = VsT + obc * LDC;
#pragma unroll
            for (int k4 = 0; k4 < TK; k4 += 4) {
                float4 p = *(const float4*)(pb + k4);
                float4 v = *(const float4*)(vb + k4);
                Ob += p.x * v.x + p.y * v.y + p.z * v.z + p.w * v.w;
            }
        }
        __syncthreads();
    }

    // ---- write partials: layout [blk][cv][q] for coalesced combine reads ----
    const int blk = (b * 16 + qt) * KSPLIT + ks;
    float* Op = g_part + (size_t)blk * 64 * 68;
#pragma unroll
    for (int i = 0; i < 4; i++)
#pragma unroll
        for (int j = 0; j < 4; j++)
            Op[(tx * 4 + j) * 64 + ty * 4 + i] = Oa[i][j];
    Op[obc * 64 + obq] = Ob;
    if (tid < 64) { g_pm[blk * 64 + tid] = mS[tid]; g_pl[blk * 64 + tid] = lS[tid]; }
}

// ---------------------------------------------------------------------------
// Combine split-KV partials + epilogue (zn descs, 2D projection, outputs)
// ---------------------------------------------------------------------------
__global__ void combine_kernel(float* __restrict__ out) {
    int gq = blockIdx.x * blockDim.x + threadIdx.x;   // 4096 queries
    int b = gq >> 10, n = gq & 1023;
    int bqt = gq >> 6;       // (b*16 + qtile)
    int r = gq & 63;

    float Mx = -CUDART_INF_F;
#pragma unroll
    for (int s = 0; s < KSPLIT; s++)
        Mx = fmaxf(Mx, g_pm[(bqt * KSPLIT + s) * 64 + r]);

    float val[68];
#pragma unroll
    for (int ch = 0; ch < 68; ch++) val[ch] = 0.f;
    float L = 0.f;
    for (int s = 0; s < KSPLIT; s++) {
        int blk = bqt * KSPLIT + s;
        float w = __expf(SCALE * (g_pm[blk * 64 + r] - Mx));
        L += g_pl[blk * 64 + r] * w;
        const float* Op = g_part + (size_t)blk * 64 * 68;
#pragma unroll
        for (int ch = 0; ch < 68; ch++) val[ch] += Op[ch * 64 + r] * w;
    }
    float invL = 1.f / L;
#pragma unroll
    for (int ch = 0; ch < 68; ch++) val[ch] *= invL;

    float x = val[64], y = val[65], z = val[66], wgt = val[67];

    // zn of desc output channels (ddof=1)
    float sum = 0.f;
#pragma unroll
    for (int c = 0; c < 64; c++) sum += val[c];
    float mean = sum * (1.f / 64.f);
    float var = 0.f;
#pragma unroll
    for (int c = 0; c < 64; c++) { float d = val[c] - mean; var += d * d; }
    float inv = rsqrtf(var * (1.f / 63.f));

    // Output layout (flattened concat of reference tuple, all float32):
    // coords (B,3,N) @0 | weights (B,1,N) @12288 | descs (B,64,N) @16384
    // | 2D (B,N,2) @278528 | valid (B,1,N) @286720
    out[(b * 3 + 0) * 1024 + n] = x;
    out[(b * 3 + 1) * 1024 + n] = y;
    out[(b * 3 + 2) * 1024 + n] = z;
    out[12288 + b * 1024 + n] = wgt;
#pragma unroll
    for (int c = 0; c < 64; c++)
        out[16384 + (b * 64 + c) * 1024 + n] = (val[c] - mean) * inv;

    float rr = sqrtf(x * x + y * y + z * z);
    float az = atan2f(y, x);
    float el = asinf(z / (rr + 1e-12f));
    float u = 0.5f * (1.0f - az * (1.0f / CUDART_PI_F)) * 1024.0f;
    float v = (1.0f - (el + 0.4363323129985824f) * (1.0f / 0.4886921905584123f)) * 64.0f;
    u = fminf(fmaxf(u, 0.f), 1023.f);
    v = fminf(fmaxf(v, 0.f), 63.f);
    out[278528 + gq * 2 + 0] = u;
    out[278528 + gq * 2 + 1] = v;

    out[286720 + b * 1024 + n] = 1.0f;   // valid_pts
}

// ---------------------------------------------------------------------------
extern "C" void kernel_launch(void* const* d_in, const int* in_sizes, int n_in,
                              void* d_out, int out_size) {
    // metadata order: src_coords (unused), tgt_coords, tgt_weights, src_desc, tgt_desc
    const float* tgt_coords = (const float*)d_in[1];
    const float* tgt_w      = (const float*)d_in[2];
    const float* src_desc   = (const float*)d_in[3];
    const float* tgt_desc   = (const float*)d_in[4];
    float* out = (float*)d_out;

    const size_t smem = (size_t)(3 * TQ * LDC + 68 * LDC + 3 * 64) * sizeof(float); // ~71.5 KB
    cudaFuncSetAttribute(attn_kernel, cudaFuncAttributeMaxDynamicSharedMemorySize, (int)smem);

    norm_src_kernel<<<16, 256>>>(src_desc);
    norm_tgt_kernel<<<1024, 256>>>(tgt_desc, tgt_coords, tgt_w);
    dim3 grid(KSPLIT, NN / TQ, BB);
    attn_kernel<<<grid, 256, smem>>>();
    combine_kernel<<<16, 256>>>(out);
}

// round 2
// speedup vs baseline: 1.0486x; 1.0486x over previous
#include <cuda_runtime.h>
#include <math_constants.h>

// Problem constants
#define BB    4
#define NN    1024      // src points per batch
#define MM    65536     // H*W target points per batch
#define CC    64        // desc channels
#define VCH   72        // padded V row stride (0..63 raw desc, 64..66 coords, 67 weight)
#define SCALE 1.5625f   // 1/(C*TEMP) = 1/(64*0.01)

#define TQ 64
#define TK 64
#define LDC 68          // padded smem row stride (floats), 272B = 16B aligned, conflict-free
#define KSPLIT 16
#define NBLK (BB*16*KSPLIT)   // 4 * (1024/64) * 16 = 1024 partial blocks

// Scratch (static __device__ arrays: allocation-free per harness rules)
__device__ float g_Q[BB*NN*CC];                       //  1 MB  [b][n][c]
__device__ float g_K[(size_t)BB*MM*CC];               // 64 MB  [b][m][c]
__device__ float g_V[(size_t)BB*MM*VCH];              // 75 MB  [b][m][cv]
__device__ float g_part[(size_t)NBLK*64*68];          // 18 MB  [blk][cv][q]
__device__ float g_pm[NBLK*64];
__device__ float g_pl[NBLK*64];

// ---------------------------------------------------------------------------
// Normalize src_desc -> Q  (zn over channel dim, ddof=1)
// ---------------------------------------------------------------------------
__global__ void norm_src_kernel(const float* __restrict__ src_desc) {
    int gid = blockIdx.x * blockDim.x + threadIdx.x;   // 4096 = B*N
    int b = gid >> 10, n = gid & 1023;
    const float* p = src_desc + (size_t)b * CC * NN + n;
    float xs[CC];
    float sum = 0.f;
#pragma unroll
    for (int c = 0; c < CC; c++) { xs[c] = p[c * NN]; sum += xs[c]; }
    float mean = sum * (1.f / 64.f);
    float var = 0.f;
#pragma unroll
    for (int c = 0; c < CC; c++) { float d = xs[c] - mean; var += d * d; }
    float inv = rsqrtf(var * (1.f / 63.f));
    float* q = g_Q + (size_t)gid * CC;
#pragma unroll
    for (int c = 0; c < CC; c++) q[c] = (xs[c] - mean) * inv;
}

// ---------------------------------------------------------------------------
// Normalize tgt_desc -> K ; pack V = [raw desc | coords | weight]
// ---------------------------------------------------------------------------
__global__ void norm_tgt_kernel(const float* __restrict__ tgt_desc,
                                const float* __restrict__ tgt_coords,
                                const float* __restrict__ tgt_w) {
    int gid = blockIdx.x * blockDim.x + threadIdx.x;   // 262144 = B*M
    int b = gid >> 16, m = gid & 65535;
    const float* p = tgt_desc + (size_t)b * CC * MM + m;
    float xs[CC];
    float sum = 0.f;
#pragma unroll
    for (int c = 0; c < CC; c++) { xs[c] = p[(size_t)c * MM]; sum += xs[c]; }
    float mean = sum * (1.f / 64.f);
    float var = 0.f;
#pragma unroll
    for (int c = 0; c < CC; c++) { float d = xs[c] - mean; var += d * d; }
    float inv = rsqrtf(var * (1.f / 63.f));
    float* kk = g_K + (size_t)gid * CC;
    float* vv = g_V + (size_t)gid * VCH;
#pragma unroll
    for (int c = 0; c < CC; c++) { kk[c] = (xs[c] - mean) * inv; vv[c] = xs[c]; }
    vv[64] = tgt_coords[(size_t)(b * 3 + 0) * MM + m];
    vv[65] = tgt_coords[(size_t)(b * 3 + 1) * MM + m];
    vv[66] = tgt_coords[(size_t)(b * 3 + 2) * MM + m];
    vv[67] = tgt_w[(size_t)b * MM + m];
}

// ---------------------------------------------------------------------------
// Fused flash attention, fp32, 4x4 register tiles, split-KV partials
// grid: (KSPLIT, N/TQ, B), block: 256
// ---------------------------------------------------------------------------
__global__ __launch_bounds__(256, 2) void attn_kernel() {
    extern __shared__ float sm[];
    float* Qs  = sm;                 // [64][LDC]  (q, c)
    float* Ks  = Qs  + TQ * LDC;     // [64][LDC]  (k, c)
    float* Ps  = Ks  + TK * LDC;     // [64][LDC]  (q, k)
    float* VsT = Ps  + TQ * LDC;     // [68][LDC]  (cv, k)
    float* mS  = VsT + 68 * LDC;     // [64]
    float* lS  = mS + 64;            // [64]
    float* cS  = lS + 64;            // [64]

    const int ks = blockIdx.x;       // key split 0..15
    const int qt = blockIdx.y;       // q tile 0..15
    const int b  = blockIdx.z;
    const int tid = threadIdx.x;
    const int ty = tid >> 4, tx = tid & 15;

    // Load Q tile (coalesced)
    const float* Qg = g_Q + ((size_t)b * NN + qt * TQ) * CC;
    for (int i = tid; i < TQ * CC; i += 256) {
        int q = i >> 6, c = i & 63;
        Qs[q * LDC + c] = Qg[q * CC + c];
    }
    if (tid < 64) { mS[tid] = -CUDART_INF_F; lS[tid] = 0.f; }

    float Oa[4][4];
#pragma unroll
    for (int i = 0; i < 4; i++)
#pragma unroll
        for (int j = 0; j < 4; j++) Oa[i][j] = 0.f;
    float Ob = 0.f;
    const int obq = tid >> 2;            // phase-2b query
    const int obc = 64 + (tid & 3);      // phase-2b channel (coords/weight)

    const int kbase = ks * (MM / KSPLIT);
    const float* Kg = g_K + ((size_t)b * MM + kbase) * CC;
    const float* Vg = g_V + ((size_t)b * MM + kbase) * VCH;

    __syncthreads();

    for (int kt = 0; kt < (MM / KSPLIT) / TK; kt++) {
        // ---- load K tile and V tile (V transposed to [cv][k]) ----
        const float* Kt = Kg + (size_t)(kt * TK) * CC;
        for (int i = tid; i < TK * CC; i += 256) {
            int k = i >> 6, c = i & 63;
            Ks[k * LDC + c] = Kt[k * CC + c];
        }
        const float* Vt = Vg + (size_t)(kt * TK) * VCH;
        for (int i = tid; i < TK * 68; i += 256) {
            int k = i / 68, cv = i - k * 68;
            VsT[cv * LDC + k] = Vt[k * VCH + cv];
        }
        __syncthreads();

        // ---- phase 1: S = Q K^T (4x4 per thread) ----
        float acc[4][4];
#pragma unroll
        for (int i = 0; i < 4; i++)
#pragma unroll
            for (int j = 0; j < 4; j++) acc[i][j] = 0.f;

        const float* qrow = Qs + (ty * 4) * LDC;
        const float* krow = Ks + (tx * 4) * LDC;
#pragma unroll
        for (int c4 = 0; c4 < CC; c4 += 4) {
            float4 av[4], bv[4];
#pragma unroll
            for (int i = 0; i < 4; i++) av[i] = *(const float4*)(qrow + i * LDC + c4);
#pragma unroll
            for (int j = 0; j < 4; j++) bv[j] = *(const float4*)(krow + j * LDC + c4);
#pragma unroll
            for (int i = 0; i < 4; i++)
#pragma unroll
                for (int j = 0; j < 4; j++)
                    acc[i][j] += av[i].x * bv[j].x + av[i].y * bv[j].y
                               + av[i].z * bv[j].z + av[i].w * bv[j].w;
        }

        // ---- online softmax bookkeeping (row groups owned by half-warps) ----
#pragma unroll
        for (int i = 0; i < 4; i++) {
            float rm = fmaxf(fmaxf(acc[i][0], acc[i][1]), fmaxf(acc[i][2], acc[i][3]));
#pragma unroll
            for (int off = 8; off > 0; off >>= 1)
                rm = fmaxf(rm, __shfl_xor_sync(0xffffffffu, rm, off));
            int q = ty * 4 + i;
            float mo = mS[q];
            float mn = fmaxf(mo, rm);
            float corr = __expf(SCALE * (mo - mn));   // -inf -> 0 on first tile
            float rs = 0.f;
#pragma unroll
            for (int j = 0; j < 4; j++) {
                float p = __expf(SCALE * (acc[i][j] - mn));
                Ps[q * LDC + tx * 4 + j] = p;
                rs += p;
            }
#pragma unroll
            for (int off = 8; off > 0; off >>= 1)
                rs += __shfl_xor_sync(0xffffffffu, rs, off);
            if (tx == 0) { mS[q] = mn; lS[q] = lS[q] * corr + rs; cS[q] = corr; }
        }
        __syncthreads();

        // ---- rescale accumulators ----
#pragma unroll
        for (int i = 0; i < 4; i++) {
            float cr = cS[ty * 4 + i];
#pragma unroll
            for (int j = 0; j < 4; j++) Oa[i][j] *= cr;
        }
        Ob *= cS[obq];

        // ---- phase 2a: O[q][0..63] += P V  (4x4 per thread) ----
        const float* prow = Ps + (ty * 4) * LDC;
        const float* vrow = VsT + (tx * 4) * LDC;
#pragma unroll
        for (int k4 = 0; k4 < TK; k4 += 4) {
            float4 pv[4], vv[4];
#pragma unroll
            for (int i = 0; i < 4; i++) pv[i] = *(const float4*)(prow + i * LDC + k4);
#pragma unroll
            for (int j = 0; j < 4; j++) vv[j] = *(const float4*)(vrow + j * LDC + k4);
#pragma unroll
            for (int i = 0; i < 4; i++)
#pragma unroll
                for (int j = 0; j < 4; j++)
                    Oa[i][j] += pv[i].x * vv[j].x + pv[i].y * vv[j].y
                              + pv[i].z * vv[j].z + pv[i].w * vv[j].w;
        }

        // ---- phase 2b: coords + weight channels (64..67) ----
        {
            const float* pb = Ps + obq * LDC;
            const float* vb = VsT + obc * LDC;
#pragma unroll
            for (int k4 = 0; k4 < TK; k4 += 4) {
                float4 p = *(const float4*)(pb + k4);
                float4 v = *(const float4*)(vb + k4);
                Ob += p.x * v.x + p.y * v.y + p.z * v.z + p.w * v.w;
            }
        }
        __syncthreads();
    }

    // ---- write partials: layout [blk][cv][q] for coalesced combine reads ----
    const int blk = (b * 16 + qt) * KSPLIT + ks;
    float* Op = g_part + (size_t)blk * 64 * 68;
#pragma unroll
    for (int i = 0; i < 4; i++)
#pragma unroll
        for (int j = 0; j < 4; j++)
            Op[(tx * 4 + j) * 64 + ty * 4 + i] = Oa[i][j];
    Op[obc * 64 + obq] = Ob;
    if (tid < 64) { g_pm[blk * 64 + tid] = mS[tid]; g_pl[blk * 64 + tid] = lS[tid]; }
}

// ---------------------------------------------------------------------------
// Combine split-KV partials + epilogue (zn descs, 2D projection, outputs)
// ---------------------------------------------------------------------------
__global__ void combine_kernel(float* __restrict__ out) {
    int gq = blockIdx.x * blockDim.x + threadIdx.x;   // 4096 queries
    int b = gq >> 10, n = gq & 1023;
    int bqt = gq >> 6;       // (b*16 + qtile)
    int r = gq & 63;

    float Mx = -CUDART_INF_F;
#pragma unroll
    for (int s = 0; s < KSPLIT; s++)
        Mx = fmaxf(Mx, g_pm[(bqt * KSPLIT + s) * 64 + r]);

    float val[68];
#pragma unroll
    for (int ch = 0; ch < 68; ch++) val[ch] = 0.f;
    float L = 0.f;
    for (int s = 0; s < KSPLIT; s++) {
        int blk = bqt * KSPLIT + s;
        float w = __expf(SCALE * (g_pm[blk * 64 + r] - Mx));
        L += g_pl[blk * 64 + r] * w;
        const float* Op = g_part + (size_t)blk * 64 * 68;
#pragma unroll
        for (int ch = 0; ch < 68; ch++) val[ch] += Op[ch * 64 + r] * w;
    }
    float invL = 1.f / L;
#pragma unroll
    for (int ch = 0; ch < 68; ch++) val[ch] *= invL;

    float x = val[64], y = val[65], z = val[66], wgt = val[67];

    // zn of desc output channels (ddof=1)
    float sum = 0.f;
#pragma unroll
    for (int c = 0; c < 64; c++) sum += val[c];
    float mean = sum * (1.f / 64.f);
    float var = 0.f;
#pragma unroll
    for (int c = 0; c < 64; c++) { float d = val[c] - mean; var += d * d; }
    float inv = rsqrtf(var * (1.f / 63.f));

    // Output layout (flattened concat of reference tuple, all float32):
    // coords (B,3,N) @0 | weights (B,1,N) @12288 | descs (B,64,N) @16384
    // | 2D (B,N,2) @278528 | valid (B,1,N) @286720
    out[(b * 3 + 0) * 1024 + n] = x;
    out[(b * 3 + 1) * 1024 + n] = y;
    out[(b * 3 + 2) * 1024 + n] = z;
    out[12288 + b * 1024 + n] = wgt;
#pragma unroll
    for (int c = 0; c < 64; c++)
        out[16384 + (b * 64 + c) * 1024 + n] = (val[c] - mean) * inv;

    float rr = sqrtf(x * x + y * y + z * z);
    float az = atan2f(y, x);
    float el = asinf(z / (rr + 1e-12f));
    float u = 0.5f * (1.0f - az * (1.0f / CUDART_PI_F)) * 1024.0f;
    float v = (1.0f - (el + 0.4363323129985824f) * (1.0f / 0.4886921905584123f)) * 64.0f;
    u = fminf(fmaxf(u, 0.f), 1023.f);
    v = fminf(fmaxf(v, 0.f), 63.f);
    out[278528 + gq * 2 + 0] = u;
    out[278528 + gq * 2 + 1] = v;

    out[286720 + b * 1024 + n] = 1.0f;   // valid_pts
}

// ---------------------------------------------------------------------------
extern "C" void kernel_launch(void* const* d_in, const int* in_sizes, int n_in,
                              void* d_out, int out_size) {
    // metadata order: src_coords (unused), tgt_coords, tgt_weights, src_desc, tgt_desc
    const float* tgt_coords = (const float*)d_in[1];
    const float* tgt_w      = (const float*)d_in[2];
    const float* src_desc   = (const float*)d_in[3];
    const float* tgt_desc   = (const float*)d_in[4];
    float* out = (float*)d_out;

    const size_t smem = (size_t)(3 * TQ * LDC + 68 * LDC + 3 * 64) * sizeof(float); // ~71.5 KB
    cudaFuncSetAttribute(attn_kernel, cudaFuncAttributeMaxDynamicSharedMemorySize, (int)smem);

    norm_src_kernel<<<16, 256>>>(src_desc);
    norm_tgt_kernel<<<1024, 256>>>(tgt_desc, tgt_coords, tgt_w);
    dim3 grid(KSPLIT, NN / TQ, BB);
    attn_kernel<<<grid, 256, smem>>>();
    combine_kernel<<<16, 256>>>(out);
}